// round 4
// baseline (speedup 1.0000x reference)
#include <cuda_runtime.h>
#include <cstdint>

#define BATCH 4194304u

// Precomputed log_softmax(W.T + b): [card*3 + action]
__device__ float    d_logp[6];
__device__ uint32_t d_one;   // opaque 1 so ptxas keeps mad.lo (fma pipe) instead of IADD3 (alu pipe)

__global__ void init_logp_kernel(const float* __restrict__ W,
                                 const float* __restrict__ bias) {
    if (threadIdx.x == 0 && blockIdx.x == 0) {
        #pragma unroll
        for (int c = 0; c < 2; c++) {
            // W is (3,2) row-major; x_a = W[a,c] + b[a]
            float x0 = W[0 * 2 + c] + bias[0];
            float x1 = W[1 * 2 + c] + bias[1];
            float x2 = W[2 * 2 + c] + bias[2];
            float m  = fmaxf(x0, fmaxf(x1, x2));
            float s0 = x0 - m, s1 = x1 - m, s2 = x2 - m;
            float l  = logf(expf(s0) + expf(s1) + expf(s2));
            d_logp[c * 3 + 0] = s0 - l;
            d_logp[c * 3 + 1] = s1 - l;
            d_logp[c * 3 + 2] = s2 - l;
        }
        d_one = 1u;
    }
}

// a*one + b on the FMA pipe (one == 1, but opaque to ptxas).
__device__ __forceinline__ uint32_t madd(uint32_t a, uint32_t b, uint32_t one) {
    uint32_t r;
    asm("mad.lo.u32 %0, %1, %2, %3;" : "=r"(r) : "r"(a), "r"(one), "r"(b));
    return r;
}

// JAX partitionable-threefry 32-bit draw for global element index i (< 2^32):
//   (o0, o1) = threefry2x32(key=(0,42), x0=hi32(i)=0, x1=lo32(i)=i); bits = o0 ^ o1
// Integer math is exact, so routing adds through IMAD is bit-identical.
__device__ __forceinline__ uint32_t tf_bits(uint32_t ctr, uint32_t one) {
    const uint32_t k0 = 0u;
    const uint32_t k1 = 42u;
    const uint32_t k2 = 0u ^ 42u ^ 0x1BD11BDAu;
    uint32_t x0 = 0u;                    // hi32(counter)=0, +k0=0 folds away
    uint32_t x1 = ctr + 42u;             // ctr + k1 (compile-time imm add)
#define TF_RND(r) { x0 = madd(x0, x1, one); x1 = __funnelshift_l(x1, x1, (r)); x1 ^= x0; }
    TF_RND(13) TF_RND(15) TF_RND(26) TF_RND(6)
    x0 = madd(x0, k1, one);      x1 = madd(x1, k2 + 1u, one);
    TF_RND(17) TF_RND(29) TF_RND(16) TF_RND(24)
    x0 = madd(x0, k2, one);      x1 = madd(x1, k0 + 2u, one);
    TF_RND(13) TF_RND(15) TF_RND(26) TF_RND(6)
    x0 = madd(x0, k0, one);      x1 = madd(x1, k1 + 3u, one);
    TF_RND(17) TF_RND(29) TF_RND(16) TF_RND(24)
    x0 = madd(x0, k1, one);      x1 = madd(x1, k2 + 4u, one);
    TF_RND(13) TF_RND(15) TF_RND(26) TF_RND(6)
    x0 = madd(x0, k2, one);      x1 = madd(x1, k0 + 5u, one);
#undef TF_RND
    return x0 ^ x1;
}

// JAX uniform(minval=tiny, maxval=1) bit-exact construction
__device__ __forceinline__ float to_unif(uint32_t bits) {
    float f = __uint_as_float((bits >> 9) | 0x3f800000u) - 1.0f;
    return fmaxf(f, 1.17549435e-38f);
}

__global__ void __launch_bounds__(256)
sample_kernel(const int* __restrict__ cards, float* __restrict__ out) {
    uint32_t b = blockIdx.x * 256u + threadIdx.x;      // grid divides BATCH exactly

    float lp[6];
    #pragma unroll
    for (int i = 0; i < 6; i++) lp[i] = d_logp[i];
    uint32_t one = d_one;

    // All 6 independent threefry chains unrolled together for ILP.
    uint32_t base = b * 6u;
    uint32_t bits[6];
    #pragma unroll
    for (int j = 0; j < 6; j++) bits[j] = tf_bits(base + (uint32_t)j, one);

    int   cf[2];
    float lcf[2];
    #pragma unroll
    for (int c = 0; c < 2; c++) {
        // score_a = logp_a + gumbel_a; gumbel = -log(-log(u)). First-max tie rule
        // (matches jnp.argmax). Bit-identical to the reference stream.
        float best = lp[c * 3 + 0] - logf(-logf(to_unif(bits[c * 3 + 0])));
        int   bi   = 0;
        #pragma unroll
        for (int a = 1; a < 3; a++) {
            float s = lp[c * 3 + a] - logf(-logf(to_unif(bits[c * 3 + a])));
            if (s > best) { best = s; bi = a; }
        }
        cf[c]  = bi;
        lcf[c] = lp[c * 3 + bi];
    }

    int card = __ldg(cards + b);         // in {0,1}
    int u0   = (card == 0) ? cf[0] : cf[1];

    float2 bel;
    if (cf[0] == cf[1])       bel = make_float2(0.5f, 0.5f);
    else if (card == 0)       bel = make_float2(1.0f, 0.0f);
    else                      bel = make_float2(0.0f, 1.0f);

    out[b] = (float)u0;
    reinterpret_cast<float2*>(out + BATCH)[b]             = bel;
    reinterpret_cast<float2*>(out + 3 * (size_t)BATCH)[b] = make_float2(lcf[0], lcf[1]);
}

extern "C" void kernel_launch(void* const* d_in, const int* in_sizes, int n_in,
                              void* d_out, int out_size) {
    const int*   cards = (const int*)d_in[0];     // cards_0: (B,) int32
    const float* W     = (const float*)d_in[1];   // (3,2) float32
    const float* bias  = (const float*)d_in[2];   // (3,) float32
    float*       out   = (float*)d_out;           // [u0(B) | beliefs(B,2) | log_cf(B,2)]

    init_logp_kernel<<<1, 32>>>(W, bias);
    sample_kernel<<<BATCH / 256, 256>>>(cards, out);
}

// round 5
// speedup vs baseline: 1.2356x; 1.2356x over previous
#include <cuda_runtime.h>
#include <cstdint>

#define BATCH 4194304u
#define LN2F  0.6931471805599453f

// Precomputed log_softmax(W.T + b), packed for vector loads:
// d_lp0 = {lp[0],lp[1],lp[2],lp[3]}, d_lp1 = {lp[4],lp[5]}  (index = card*3+action)
__device__ float4 d_lp0;
__device__ float2 d_lp1;

__global__ void init_logp_kernel(const float* __restrict__ W,
                                 const float* __restrict__ bias) {
    if (threadIdx.x == 0 && blockIdx.x == 0) {
        float lp[6];
        #pragma unroll
        for (int c = 0; c < 2; c++) {
            // W is (3,2) row-major; x_a = W[a,c] + b[a]
            float x0 = W[0 * 2 + c] + bias[0];
            float x1 = W[1 * 2 + c] + bias[1];
            float x2 = W[2 * 2 + c] + bias[2];
            float m  = fmaxf(x0, fmaxf(x1, x2));
            float s0 = x0 - m, s1 = x1 - m, s2 = x2 - m;
            float l  = logf(expf(s0) + expf(s1) + expf(s2));
            lp[c * 3 + 0] = s0 - l;
            lp[c * 3 + 1] = s1 - l;
            lp[c * 3 + 2] = s2 - l;
        }
        d_lp0 = make_float4(lp[0], lp[1], lp[2], lp[3]);
        d_lp1 = make_float2(lp[4], lp[5]);
    }
}

// JAX partitionable-threefry 32-bit draw for global element index i (< 2^32):
//   (o0, o1) = threefry2x32(key=(0,42), x0=hi32(i)=0, x1=lo32(i)=i); bits = o0 ^ o1
__device__ __forceinline__ uint32_t tf_bits(uint32_t ctr) {
    const uint32_t k1 = 42u;
    const uint32_t k2 = 42u ^ 0x1BD11BDAu;
    uint32_t x0 = 0u;            // hi32 + k0 = 0
    uint32_t x1 = ctr + 42u;
#define TF_RND(r) { x0 += x1; x1 = __funnelshift_l(x1, x1, (r)); x1 ^= x0; }
    TF_RND(13) TF_RND(15) TF_RND(26) TF_RND(6)
    x0 += k1; x1 += k2 + 1u;
    TF_RND(17) TF_RND(29) TF_RND(16) TF_RND(24)
    x0 += k2; x1 += 2u;
    TF_RND(13) TF_RND(15) TF_RND(26) TF_RND(6)
    x1 += k1 + 3u;               // x0 += k0 folds away
    TF_RND(17) TF_RND(29) TF_RND(16) TF_RND(24)
    x0 += k1; x1 += k2 + 4u;
    TF_RND(13) TF_RND(15) TF_RND(26) TF_RND(6)
    x0 += k2; x1 += 5u;
#undef TF_RND
    return x0 ^ x1;
}

// JAX uniform(minval=tiny, maxval=1) bit-exact construction
__device__ __forceinline__ float to_unif(uint32_t bits) {
    float f = __uint_as_float((bits >> 9) | 0x3f800000u) - 1.0f;
    return fmaxf(f, 1.17549435e-38f);
}

__global__ void __launch_bounds__(256)
sample_kernel(const int* __restrict__ cards, float* __restrict__ out) {
    uint32_t b = blockIdx.x * 256u + threadIdx.x;   // grid divides BATCH exactly

    float4 lpA = d_lp0;
    float2 lpB = d_lp1;
    float  lp[6] = {lpA.x, lpA.y, lpA.z, lpA.w, lpB.x, lpB.y};

    // 6 independent threefry chains, interleaved for ILP.
    uint32_t base = b * 6u;
    float u[6];
    #pragma unroll
    for (int j = 0; j < 6; j++) u[j] = to_unif(tf_bits(base + (uint32_t)j));

    // Fast Gumbel scores: s = lp - ln(-ln u) via MUFU.LG2.
    // Scores are never output; only argmax decisions matter, and those are
    // guarded below so they are bit-exact vs the precise-log reference.
    float s[6];
    float umax = 0.0f;
    #pragma unroll
    for (int j = 0; j < 6; j++) {
        float v = __log2f(u[j]) * (-LN2F);          // ≈ -ln u  (>0)
        s[j] = fmaf(__log2f(v), -LN2F, lp[j]);      // ≈ lp - ln v
        umax = fmaxf(umax, u[j]);
    }

    int   cf[2];
    float lcf[2];
    float mingap = 1e30f;
    #pragma unroll
    for (int c = 0; c < 2; c++) {
        float s0 = s[c * 3], s1 = s[c * 3 + 1], s2 = s[c * 3 + 2];
        // first-max tie rule (matches jnp.argmax)
        int   bi = 0;
        float best = s0;
        if (s1 > best) { best = s1; bi = 1; }
        if (s2 > best) { best = s2; bi = 2; }
        // second largest of three
        float mx01 = fmaxf(s0, s1), mn01 = fminf(s0, s1);
        float second = fminf(mx01, fmaxf(mn01, s2));
        mingap = fminf(mingap, best - second);
        cf[c]  = bi;
        lcf[c] = lp[c * 3 + bi];
    }

    // Guard: fast-chain score abs error <= ~5e-4 when u <= 0.999. If the gap is
    // small or any u is near 1, redo this thread with precise logf (bit-exact
    // vs XLA's -log(-log(u)) + logp argmax).
    if (mingap < 2e-3f || umax > 0.999f) {
        #pragma unroll
        for (int c = 0; c < 2; c++) {
            float best = lp[c * 3] - logf(-logf(u[c * 3]));
            int   bi   = 0;
            #pragma unroll
            for (int a = 1; a < 3; a++) {
                float sp = lp[c * 3 + a] - logf(-logf(u[c * 3 + a]));
                if (sp > best) { best = sp; bi = a; }
            }
            cf[c]  = bi;
            lcf[c] = lp[c * 3 + bi];
        }
    }

    int card = __ldg(cards + b);         // in {0,1}
    int u0   = (card == 0) ? cf[0] : cf[1];

    float2 bel;
    if (cf[0] == cf[1])       bel = make_float2(0.5f, 0.5f);
    else if (card == 0)       bel = make_float2(1.0f, 0.0f);
    else                      bel = make_float2(0.0f, 1.0f);

    out[b] = (float)u0;
    reinterpret_cast<float2*>(out + BATCH)[b]             = bel;
    reinterpret_cast<float2*>(out + 3 * (size_t)BATCH)[b] = make_float2(lcf[0], lcf[1]);
}

extern "C" void kernel_launch(void* const* d_in, const int* in_sizes, int n_in,
                              void* d_out, int out_size) {
    const int*   cards = (const int*)d_in[0];     // cards_0: (B,) int32
    const float* W     = (const float*)d_in[1];   // (3,2) float32
    const float* bias  = (const float*)d_in[2];   // (3,) float32
    float*       out   = (float*)d_out;           // [u0(B) | beliefs(B,2) | log_cf(B,2)]

    init_logp_kernel<<<1, 32>>>(W, bias);
    sample_kernel<<<BATCH / 256, 256>>>(cards, out);
}

// round 6
// speedup vs baseline: 1.2939x; 1.0472x over previous
#include <cuda_runtime.h>
#include <cstdint>

#define BATCH    4194304u
#define INV_LN2  1.4426950408889634f
// k > KPATCH  <=>  t = 23 - log2(k) < ~1e-3  (u > ~0.99931): patch t with precise logf
#define KPATCH   8382700u

// Per (card,action) index j = card*3 + action:
//   d_lp[j] = log_softmax(W.T + b)   (output value)
//   d_w[j]  = exp(-lp[j])            (argmin weight: argmax lp - ln(-ln u) == argmin t*w)
__device__ float d_lp[6];
__device__ float d_w[6];

__global__ void init_logp_kernel(const float* __restrict__ W,
                                 const float* __restrict__ bias) {
    if (threadIdx.x == 0 && blockIdx.x == 0) {
        #pragma unroll
        for (int c = 0; c < 2; c++) {
            // W is (3,2) row-major; x_a = W[a,c] + b[a]
            float x0 = W[0 * 2 + c] + bias[0];
            float x1 = W[1 * 2 + c] + bias[1];
            float x2 = W[2 * 2 + c] + bias[2];
            float m  = fmaxf(x0, fmaxf(x1, x2));
            float s0 = x0 - m, s1 = x1 - m, s2 = x2 - m;
            float l  = logf(expf(s0) + expf(s1) + expf(s2));
            float lp0 = s0 - l, lp1 = s1 - l, lp2 = s2 - l;
            d_lp[c * 3 + 0] = lp0;  d_w[c * 3 + 0] = expf(-lp0);
            d_lp[c * 3 + 1] = lp1;  d_w[c * 3 + 1] = expf(-lp1);
            d_lp[c * 3 + 2] = lp2;  d_w[c * 3 + 2] = expf(-lp2);
        }
    }
}

// JAX partitionable-threefry 32-bit draw for global element index i (< 2^32):
//   (o0, o1) = threefry2x32(key=(0,42), x0=hi32(i)=0, x1=lo32(i)=i); bits = o0 ^ o1
__device__ __forceinline__ uint32_t tf_bits(uint32_t ctr) {
    const uint32_t k1 = 42u;
    const uint32_t k2 = 42u ^ 0x1BD11BDAu;
    uint32_t x0 = 0u;            // hi32 + k0 = 0
    uint32_t x1 = ctr + 42u;
#define TF_RND(r) { x0 += x1; x1 = __funnelshift_l(x1, x1, (r)); x1 ^= x0; }
    TF_RND(13) TF_RND(15) TF_RND(26) TF_RND(6)
    x0 += k1; x1 += k2 + 1u;
    TF_RND(17) TF_RND(29) TF_RND(16) TF_RND(24)
    x0 += k2; x1 += 2u;
    TF_RND(13) TF_RND(15) TF_RND(26) TF_RND(6)
    x1 += k1 + 3u;               // x0 += k0 folds away
    TF_RND(17) TF_RND(29) TF_RND(16) TF_RND(24)
    x0 += k1; x1 += k2 + 4u;
    TF_RND(13) TF_RND(15) TF_RND(26) TF_RND(6)
    x0 += k2; x1 += 5u;
#undef TF_RND
    return x0 ^ x1;
}

__global__ void __launch_bounds__(256)
sample_kernel(const int* __restrict__ cards, float* __restrict__ out) {
    uint32_t b   = blockIdx.x * 256u + threadIdx.x;   // grid divides BATCH exactly
    int     card = __ldg(cards + b);                  // in {0,1}; issue early

    float lp[6], w[6];
    #pragma unroll
    for (int i = 0; i < 6; i++) { lp[i] = d_lp[i]; w[i] = d_w[i]; }

    // 6 independent threefry chains, interleaved for ILP.
    uint32_t base = b * 6u;
    uint32_t k[6];
    #pragma unroll
    for (int j = 0; j < 6; j++) k[j] = tf_bits(base + (uint32_t)j) >> 9;  // 23-bit mantissa bits

    // u = k * 2^-23 (exact; JAX's (bits>>9|0x3f800000)-1).  t = -log2(u) = 23 - log2(k).
    // MUFU.LG2 on float(k): exponent part exact -> |t_err| <= ~3e-7 absolute.
    float kf[6], t[6];
    #pragma unroll
    for (int j = 0; j < 6; j++) {
        kf[j] = (float)k[j];
        t[j]  = 23.0f - __log2f(kf[j]);
    }
    // Patch tiny-t draws (u near 1) with precise logf; rare (P ~ 7e-4/draw).
    #pragma unroll
    for (int j = 0; j < 6; j++)
        if (k[j] > KPATCH) t[j] = fmaf(logf(kf[j]), -INV_LN2, 23.0f);

    // argmax_a lp_a - ln(-ln u_a)  ==  argmin_a t_a * w_a   (exact monotone map).
    int   cf[2];
    float lcf[2];
    bool  need_exact = false;
    #pragma unroll
    for (int c = 0; c < 2; c++) {
        float p0 = t[c * 3 + 0] * w[c * 3 + 0];
        float p1 = t[c * 3 + 1] * w[c * 3 + 1];
        float p2 = t[c * 3 + 2] * w[c * 3 + 2];
        int   bi = 0;
        float best = p0;
        if (p1 < best) { best = p1; bi = 1; }
        if (p2 < best) { best = p2; bi = 2; }
        // second-smallest = median of three
        float second = fmaxf(fminf(p0, p1), fminf(fmaxf(p0, p1), p2));
        // relative-gap guard: fast rel error <= ~3e-4; eps = 1e-3 (3x margin)
        need_exact |= (second < fmaf(best, 1e-3f, best));
        cf[c]  = bi;
        lcf[c] = lp[c * 3 + bi];
    }

    if (need_exact) {
        // Bit-exact reference arithmetic: u = max(k*2^-23, tiny); score = lp - log(-log u)
        #pragma unroll
        for (int c = 0; c < 2; c++) {
            int bi = 0;
            float best = -1e30f;
            #pragma unroll
            for (int a = 0; a < 3; a++) {
                float u = fmaxf(kf[c * 3 + a] * 0x1p-23f, 1.17549435e-38f);
                float s = lp[c * 3 + a] - logf(-logf(u));
                if (s > best) { best = s; bi = a; }     // first-max tie rule
            }
            cf[c]  = bi;
            lcf[c] = lp[c * 3 + bi];
        }
    }

    int u0 = (card == 0) ? cf[0] : cf[1];

    float2 bel;
    if (cf[0] == cf[1])       bel = make_float2(0.5f, 0.5f);
    else if (card == 0)       bel = make_float2(1.0f, 0.0f);
    else                      bel = make_float2(0.0f, 1.0f);

    out[b] = (float)u0;
    reinterpret_cast<float2*>(out + BATCH)[b]             = bel;
    reinterpret_cast<float2*>(out + 3 * (size_t)BATCH)[b] = make_float2(lcf[0], lcf[1]);
}

extern "C" void kernel_launch(void* const* d_in, const int* in_sizes, int n_in,
                              void* d_out, int out_size) {
    const int*   cards = (const int*)d_in[0];     // cards_0: (B,) int32
    const float* W     = (const float*)d_in[1];   // (3,2) float32
    const float* bias  = (const float*)d_in[2];   // (3,) float32
    float*       out   = (float*)d_out;           // [u0(B) | beliefs(B,2) | log_cf(B,2)]

    init_logp_kernel<<<1, 32>>>(W, bias);
    sample_kernel<<<BATCH / 256, 256>>>(cards, out);
}